// round 9
// baseline (speedup 1.0000x reference)
#include <cuda_runtime.h>
#include <cuda_bf16.h>
#include <cstdint>

#define B_  4
#define T_  2048
#define C_  1024
#define NH_ 16
#define HS_ 64
#define M_  (B_*T_)      // 8192

#define QSCALE 0.18033688011112042f   // 0.125 * log2(e)

// ---------------- scratch (__device__ globals; no allocation) ---------------
__device__ __nv_bfloat16 g_qh[B_*NH_*T_*HS_];   // [B,NH,T,HS] bf16 splits
__device__ __nv_bfloat16 g_ql[B_*NH_*T_*HS_];
__device__ __nv_bfloat16 g_kh[B_*NH_*T_*HS_];
__device__ __nv_bfloat16 g_kl[B_*NH_*T_*HS_];
__device__ __nv_bfloat16 g_vh[B_*NH_*T_*HS_];
__device__ __nv_bfloat16 g_vl[B_*NH_*T_*HS_];
__device__ __nv_bfloat16 g_ah[M_*C_];           // activation hi (x, then y)
__device__ __nv_bfloat16 g_al[M_*C_];
__device__ __nv_bfloat16 g_wqh[3*C_*C_];
__device__ __nv_bfloat16 g_wql[3*C_*C_];
__device__ __nv_bfloat16 g_wph[C_*C_];
__device__ __nv_bfloat16 g_wpl[C_*C_];

// ---------------- helpers ---------------------------------------------------
__device__ __forceinline__ uint32_t smem_u32(const void* p) {
    uint32_t a;
    asm("{ .reg .u64 t; cvta.to.shared.u64 t, %1; cvt.u32.u64 %0, t; }" : "=r"(a) : "l"(p));
    return a;
}
#define LDMX4(r0, r1, r2, r3, addr)                                              \
    asm volatile("ldmatrix.sync.aligned.m8n8.x4.shared.b16 {%0,%1,%2,%3}, [%4];" \
        : "=r"(r0), "=r"(r1), "=r"(r2), "=r"(r3) : "r"(addr))
#define LDMX4T(r0, r1, r2, r3, addr)                                             \
    asm volatile("ldmatrix.sync.aligned.m8n8.x4.trans.shared.b16 {%0,%1,%2,%3}, [%4];" \
        : "=r"(r0), "=r"(r1), "=r"(r2), "=r"(r3) : "r"(addr))
#define MMA16816(d, a0, a1, a2, a3, b0, b1)                                      \
    asm volatile("mma.sync.aligned.m16n8k16.row.col.f32.bf16.bf16.f32 "          \
        "{%0,%1,%2,%3}, {%4,%5,%6,%7}, {%8,%9}, {%0,%1,%2,%3};"                  \
        : "+f"((d)[0]), "+f"((d)[1]), "+f"((d)[2]), "+f"((d)[3])                 \
        : "r"(a0), "r"(a1), "r"(a2), "r"(a3), "r"(b0), "r"(b1))
#define CP16(dst, src)                                                            \
    asm volatile("cp.async.cg.shared.global [%0], [%1], 16;" :: "r"(dst), "l"(src))
#define CPCOMMIT() asm volatile("cp.async.commit_group;")
#define CPWAIT1()  asm volatile("cp.async.wait_group 1;")
#define CPWAIT0()  asm volatile("cp.async.wait_group 0;")

__device__ __forceinline__ float ex2f(float x) {
    float r;
    asm("ex2.approx.ftz.f32 %0, %1;" : "=f"(r) : "f"(x));
    return r;
}
__device__ __forceinline__ float rcpf(float x) {
    float r;
    asm("rcp.approx.ftz.f32 %0, %1;" : "=f"(r) : "f"(x));
    return r;
}
__device__ __forceinline__ void split2(float x, float y, uint32_t& hi, uint32_t& lo) {
    __nv_bfloat16 hx = __float2bfloat16_rn(x), hy = __float2bfloat16_rn(y);
    __nv_bfloat162 h; h.x = hx; h.y = hy;
    __nv_bfloat162 l;
    l.x = __float2bfloat16_rn(x - __bfloat162float(hx));
    l.y = __float2bfloat16_rn(y - __bfloat162float(hy));
    hi = *(uint32_t*)&h; lo = *(uint32_t*)&l;
}

// ---------------- split fp32 -> bf16 hi/lo ----------------------------------
__global__ __launch_bounds__(256)
void split_kernel(const float* __restrict__ src, __nv_bfloat16* __restrict__ hi,
                  __nv_bfloat16* __restrict__ lo, int n4)
{
    int i = blockIdx.x * 256 + threadIdx.x;
    if (i >= n4) return;
    float4 v = ((const float4*)src)[i];
    uint32_t h0, l0, h1, l1;
    split2(v.x, v.y, h0, l0);
    split2(v.z, v.w, h1, l1);
    ((uint32_t*)hi)[i*2]   = h0;
    ((uint32_t*)hi)[i*2+1] = h1;
    ((uint32_t*)lo)[i*2]   = l0;
    ((uint32_t*)lo)[i*2+1] = l1;
}

// ---------------- HMMA GEMM (cp.async 3-stage, 128x256 CTA, 64x64 warp) ------
// Out[m,n] = sum_k A[m,k]*W[n,k] + bias[n]; bf16x3 (Ah*Wh + Ah*Wl + Al*Wh).
// CTA 128x256, BK=32, 8 warps (2M x 4N), warp 64x64 -> 172 B smem per MMA.
// MODE 1: epilogue splits to g_q*/g_k*/g_v* bf16 hi/lo (q scaled by QSCALE).
// MODE 2: Out = fp32 + bias.
#define PADK 40                       // bf16 per smem row (80 B)
#define GA_STAGE (128*PADK*2)         // 10240 B
#define GB_STAGE (256*PADK*2)         // 20480 B
#define GSTAGE   (GA_STAGE + GB_STAGE)
#define GSMEM_BYTES (3 * GSTAGE)      // 92160 B

template <int MODE>
__global__ __launch_bounds__(256, 1)
void gemm_hmma(const __nv_bfloat16* __restrict__ Ah, const __nv_bfloat16* __restrict__ Al,
               const __nv_bfloat16* __restrict__ Wh, const __nv_bfloat16* __restrict__ Wl,
               const float* __restrict__ bias, float* __restrict__ Out)
{
    extern __shared__ __nv_bfloat16 gsm[];
    const uint32_t sbase = smem_u32(gsm);
    const int tid  = threadIdx.x;
    const int bm   = blockIdx.y, bn = blockIdx.x;
    const int warp = tid >> 5, lane = tid & 31;
    const int warpM = warp & 1, warpN = warp >> 1;   // 2 x 4

    // loader geometry: A row tid>>1 (16 cols at (tid&1)*16), B row tid (32 cols)
    const int lrowA = tid >> 1;
    const int lcolA = (tid & 1) * 16;
    const size_t arowoff = (size_t)(bm * 128 + lrowA) * C_ + lcolA;
    const size_t browoff = (size_t)(bn * 256 + tid) * C_;
    const uint32_t aOff = (uint32_t)(lrowA * PADK + lcolA) * 2;
    const uint32_t bOff = (uint32_t)(tid * PADK) * 2;

    // ldmatrix lane addressing
    const int rowA_l = warpM * 64 + (lane & 15);        // + mf*16
    const int colA_l = (lane >> 4) * 8;
    const int rowB_l = warpN * 64 + (lane & 7) + ((lane >> 4) << 3);  // + nf*16
    const int colB_l = ((lane >> 3) & 1) * 8;

    float acc[4][8][4];
#pragma unroll
    for (int mf = 0; mf < 4; mf++)
#pragma unroll
        for (int nf = 0; nf < 8; nf++)
#pragma unroll
            for (int r = 0; r < 4; r++) acc[mf][nf][r] = 0.f;

    const int NIT = 96;  // 3 passes * 32

    auto issue = [&](int s, int it) {
        const int pass = it >> 5;
        const int kb = (it & 31) * 32;
        const __nv_bfloat16* Ap = (pass < 2) ? Ah : Al;
        const __nv_bfloat16* Wp = (pass == 1) ? Wl : Wh;
        const uint32_t aDst = sbase + (uint32_t)s * GSTAGE + aOff;
        CP16(aDst,      Ap + arowoff + kb);
        CP16(aDst + 16, Ap + arowoff + kb + 8);
        const uint32_t bDst = sbase + (uint32_t)s * GSTAGE + GA_STAGE + bOff;
#pragma unroll
        for (int c = 0; c < 4; c++)
            CP16(bDst + c * 16, Wp + browoff + kb + c * 8);
    };

    issue(0, 0); CPCOMMIT();
    issue(1, 1); CPCOMMIT();

    for (int it = 0; it < NIT; it++) {
        CPWAIT1();
        __syncthreads();
        if (it + 2 < NIT) issue((it + 2) % 3, it + 2);
        CPCOMMIT();
        const uint32_t aBase = sbase + (uint32_t)(it % 3) * GSTAGE;
        const uint32_t bBase = aBase + GA_STAGE;
#pragma unroll
        for (int k16 = 0; k16 < 2; k16++) {
            uint32_t a[4][4];
#pragma unroll
            for (int mf = 0; mf < 4; mf++)
                LDMX4(a[mf][0], a[mf][1], a[mf][2], a[mf][3],
                      aBase + (uint32_t)((rowA_l + mf * 16) * PADK + colA_l + k16 * 16) * 2);
#pragma unroll
            for (int nf = 0; nf < 4; nf++) {
                uint32_t b[4];
                LDMX4(b[0], b[1], b[2], b[3],
                      bBase + (uint32_t)((rowB_l + nf * 16) * PADK + colB_l + k16 * 16) * 2);
#pragma unroll
                for (int mf = 0; mf < 4; mf++) {
                    MMA16816(acc[mf][nf*2],   a[mf][0], a[mf][1], a[mf][2], a[mf][3], b[0], b[1]);
                    MMA16816(acc[mf][nf*2+1], a[mf][0], a[mf][1], a[mf][2], a[mf][3], b[2], b[3]);
                }
            }
        }
    }

    // ---------------- epilogue ----------------
    const int mrow0 = bm * 128 + warpM * 64;
    const int ncol0 = bn * 256 + warpN * 64;
    const int lq = lane >> 2, lr = lane & 3;
#pragma unroll
    for (int mf = 0; mf < 4; mf++) {
#pragma unroll
        for (int nf = 0; nf < 8; nf++) {
            const int n = ncol0 + nf * 8 + lr * 2;
            const float b0 = bias[n], b1 = bias[n + 1];
#pragma unroll
            for (int half = 0; half < 2; half++) {
                const int m = mrow0 + mf * 16 + lq + half * 8;
                float v0 = acc[mf][nf][half * 2 + 0] + b0;
                float v1 = acc[mf][nf][half * 2 + 1] + b1;
                if (MODE == 1) {
                    const int sel = n >> 10;
                    if (sel == 0) { v0 *= QSCALE; v1 *= QSCALE; }
                    __nv_bfloat16* dh = (sel == 0) ? g_qh : (sel == 1) ? g_kh : g_vh;
                    __nv_bfloat16* dl = (sel == 0) ? g_ql : (sel == 1) ? g_kl : g_vl;
                    const int h   = (n & 1023) >> 6;
                    const int hs0 = n & 63;
                    const int bb = m >> 11, t = m & 2047;
                    const size_t idx = (((size_t)(bb * NH_ + h) * T_ + t) << 6) + hs0;
                    uint32_t hi, lo;
                    split2(v0, v1, hi, lo);
                    *(uint32_t*)(dh + idx) = hi;
                    *(uint32_t*)(dl + idx) = lo;
                } else {
                    float2 v; v.x = v0; v.y = v1;
                    *(float2*)(Out + (size_t)m * C_ + n) = v;
                }
            }
        }
    }
}

// ---------------- HMMA flash attention (unchanged, known good) ---------------
#define AP 72                         // padded row stride (bf16)
#define SQH 0
#define SQL (128*AP)
#define SKV0 (2*128*AP)
#define KVSTAGE (4*64*AP)
#define ATTN_SMEM_BYTES ((SKV0 + 2*KVSTAGE) * 2)   // 110592 B

__global__ __launch_bounds__(256, 2)
void attn_hmma()
{
    extern __shared__ __nv_bfloat16 asm_[];
    const uint32_t sbase = smem_u32(asm_);
    const int tid  = threadIdx.x;
    const int warp = tid >> 5, lane = tid & 31;
    const int lq = lane >> 2, lr = lane & 3;

    const int qt = (int)gridDim.x - 1 - (int)blockIdx.x;
    const int h  = blockIdx.y;
    const int b  = blockIdx.z;
    const size_t bh = (size_t)(b * NH_ + h) * (T_ * HS_);

#pragma unroll
    for (int i = 0; i < 4; i++) {
        int c = i * 256 + tid;
        int row = c >> 3, col = (c & 7) * 8;
        const size_t src = bh + (size_t)(qt * 128 + row) * 64 + col;
        *(uint4*)(asm_ + SQH + row * AP + col) = *(const uint4*)(g_qh + src);
        *(uint4*)(asm_ + SQL + row * AP + col) = *(const uint4*)(g_ql + src);
    }

    auto issue_kv = [&](int s, int kv) {
        const uint32_t stg = sbase + (uint32_t)(SKV0 + s * KVSTAGE) * 2;
#pragma unroll
        for (int i = 0; i < 2; i++) {
            int c = i * 256 + tid;
            int row = c >> 3, col = (c & 7) * 8;
            const size_t src = bh + (size_t)(kv * 64 + row) * 64 + col;
            const uint32_t d = stg + (uint32_t)(row * AP + col) * 2;
            CP16(d,               g_kh + src);
            CP16(d + (64*AP)*2,   g_kl + src);
            CP16(d + (2*64*AP)*2, g_vh + src);
            CP16(d + (3*64*AP)*2, g_vl + src);
        }
    };

    const int kvmax = 2 * qt + 1;
    issue_kv(0, 0); CPCOMMIT();

    const int mr = qt * 128 + warp * 16;
    float m0 = -1e30f, m1 = -1e30f, l0 = 0.f, l1 = 0.f;
    float oacc[8][4];
#pragma unroll
    for (int d = 0; d < 8; d++)
#pragma unroll
        for (int r = 0; r < 4; r++) oacc[d][r] = 0.f;

    const uint32_t qhB = sbase + SQH * 2;
    const uint32_t qlB = sbase + SQL * 2;
    const int rowA_l = warp * 16 + (lane & 15);
    const int colA_l = (lane >> 4) * 8;
    const int rowB_l = (lane & 7) + ((lane >> 4) << 3);
    const int colB_l = ((lane >> 3) & 1) * 8;

    for (int kv = 0; kv <= kvmax; kv++) {
        CPWAIT0();
        __syncthreads();
        if (kv < kvmax) issue_kv((kv + 1) & 1, kv + 1);
        CPCOMMIT();

        const int nc = kv * 64;
        if (nc <= mr + 15) {
            const uint32_t stg = sbase + (uint32_t)(SKV0 + (kv & 1) * KVSTAGE) * 2;
            const uint32_t khB = stg;
            const uint32_t klB = stg + (64*AP)*2;
            const uint32_t vhB = stg + (2*64*AP)*2;
            const uint32_t vlB = stg + (3*64*AP)*2;

            float s[8][4];
#pragma unroll
            for (int jn = 0; jn < 8; jn++)
#pragma unroll
                for (int r = 0; r < 4; r++) s[jn][r] = 0.f;

#pragma unroll
            for (int pass = 0; pass < 3; pass++) {
                const uint32_t aB = (pass < 2) ? qhB : qlB;
                const uint32_t bB = (pass == 1) ? klB : khB;
#pragma unroll
                for (int k16 = 0; k16 < 4; k16++) {
                    uint32_t a[4];
                    LDMX4(a[0], a[1], a[2], a[3],
                          aB + (uint32_t)(rowA_l * AP + k16 * 16 + colA_l) * 2);
#pragma unroll
                    for (int nb = 0; nb < 4; nb++) {
                        uint32_t bb[4];
                        LDMX4(bb[0], bb[1], bb[2], bb[3],
                              bB + (uint32_t)((nb * 16 + rowB_l) * AP + k16 * 16 + colB_l) * 2);
                        MMA16816(s[nb*2],   a[0], a[1], a[2], a[3], bb[0], bb[1]);
                        MMA16816(s[nb*2+1], a[0], a[1], a[2], a[3], bb[2], bb[3]);
                    }
                }
            }

            if (nc + 63 > mr) {
#pragma unroll
                for (int jn = 0; jn < 8; jn++)
#pragma unroll
                    for (int e = 0; e < 2; e++) {
                        const int col = nc + jn * 8 + lr * 2 + e;
                        if (col > mr + lq)     s[jn][e]     = -1e30f;
                        if (col > mr + lq + 8) s[jn][e + 2] = -1e30f;
                    }
            }

            float mx0 = -1e30f, mx1 = -1e30f;
#pragma unroll
            for (int jn = 0; jn < 8; jn++) {
                mx0 = fmaxf(mx0, fmaxf(s[jn][0], s[jn][1]));
                mx1 = fmaxf(mx1, fmaxf(s[jn][2], s[jn][3]));
            }
            mx0 = fmaxf(mx0, __shfl_xor_sync(0xffffffffu, mx0, 1));
            mx0 = fmaxf(mx0, __shfl_xor_sync(0xffffffffu, mx0, 2));
            mx1 = fmaxf(mx1, __shfl_xor_sync(0xffffffffu, mx1, 1));
            mx1 = fmaxf(mx1, __shfl_xor_sync(0xffffffffu, mx1, 2));
            const float mn0 = fmaxf(m0, mx0), mn1 = fmaxf(m1, mx1);
            const float c0 = ex2f(m0 - mn0), c1 = ex2f(m1 - mn1);
            m0 = mn0; m1 = mn1;
            float rs0 = 0.f, rs1 = 0.f;
#pragma unroll
            for (int jn = 0; jn < 8; jn++) {
                s[jn][0] = ex2f(s[jn][0] - mn0);
                s[jn][1] = ex2f(s[jn][1] - mn0);
                s[jn][2] = ex2f(s[jn][2] - mn1);
                s[jn][3] = ex2f(s[jn][3] - mn1);
                rs0 += s[jn][0] + s[jn][1];
                rs1 += s[jn][2] + s[jn][3];
            }
            rs0 += __shfl_xor_sync(0xffffffffu, rs0, 1);
            rs0 += __shfl_xor_sync(0xffffffffu, rs0, 2);
            rs1 += __shfl_xor_sync(0xffffffffu, rs1, 1);
            rs1 += __shfl_xor_sync(0xffffffffu, rs1, 2);
            l0 = l0 * c0 + rs0;
            l1 = l1 * c1 + rs1;
#pragma unroll
            for (int d = 0; d < 8; d++) {
                oacc[d][0] *= c0; oacc[d][1] *= c0;
                oacc[d][2] *= c1; oacc[d][3] *= c1;
            }

            uint32_t ph[4][4], pl[4][4];
#pragma unroll
            for (int kk = 0; kk < 4; kk++) {
                const int j0 = kk * 2, j1 = kk * 2 + 1;
                split2(s[j0][0], s[j0][1], ph[kk][0], pl[kk][0]);
                split2(s[j0][2], s[j0][3], ph[kk][1], pl[kk][1]);
                split2(s[j1][0], s[j1][1], ph[kk][2], pl[kk][2]);
                split2(s[j1][2], s[j1][3], ph[kk][3], pl[kk][3]);
            }

#pragma unroll
            for (int kk = 0; kk < 4; kk++) {
#pragma unroll
                for (int db = 0; db < 4; db++) {
                    uint32_t v[4];
                    LDMX4T(v[0], v[1], v[2], v[3],
                           vhB + (uint32_t)((kk * 16 + (lane & 15)) * AP + db * 16 + colA_l) * 2);
                    MMA16816(oacc[db*2],   ph[kk][0], ph[kk][1], ph[kk][2], ph[kk][3], v[0], v[1]);
                    MMA16816(oacc[db*2+1], ph[kk][0], ph[kk][1], ph[kk][2], ph[kk][3], v[2], v[3]);
                    MMA16816(oacc[db*2],   pl[kk][0], pl[kk][1], pl[kk][2], pl[kk][3], v[0], v[1]);
                    MMA16816(oacc[db*2+1], pl[kk][0], pl[kk][1], pl[kk][2], pl[kk][3], v[2], v[3]);
                    LDMX4T(v[0], v[1], v[2], v[3],
                           vlB + (uint32_t)((kk * 16 + (lane & 15)) * AP + db * 16 + colA_l) * 2);
                    MMA16816(oacc[db*2],   ph[kk][0], ph[kk][1], ph[kk][2], ph[kk][3], v[0], v[1]);
                    MMA16816(oacc[db*2+1], ph[kk][0], ph[kk][1], ph[kk][2], ph[kk][3], v[2], v[3]);
                }
            }
        }
        __syncthreads();
    }

    const float inv0 = rcpf(l0), inv1 = rcpf(l1);
    const int t0 = qt * 128 + warp * 16 + lq;
    const size_t base0 = ((size_t)b * T_ + t0) * C_ + h * 64;
    const size_t base1 = base0 + (size_t)8 * C_;
#pragma unroll
    for (int jn = 0; jn < 8; jn++) {
        const int col = jn * 8 + lr * 2;
        uint32_t hi, lo;
        split2(oacc[jn][0] * inv0, oacc[jn][1] * inv0, hi, lo);
        *(uint32_t*)(g_ah + base0 + col) = hi;
        *(uint32_t*)(g_al + base0 + col) = lo;
        split2(oacc[jn][2] * inv1, oacc[jn][3] * inv1, hi, lo);
        *(uint32_t*)(g_ah + base1 + col) = hi;
        *(uint32_t*)(g_al + base1 + col) = lo;
    }
}

// ---------------------------------------------------------------------------
extern "C" void kernel_launch(void* const* d_in, const int* in_sizes, int n_in,
                              void* d_out, int out_size)
{
    (void)in_sizes; (void)n_in; (void)out_size;
    const float* x     = (const float*)d_in[0];
    const float* Wqkv  = (const float*)d_in[1];
    const float* bqkv  = (const float*)d_in[2];
    const float* Wproj = (const float*)d_in[3];
    const float* bproj = (const float*)d_in[4];
    float* out = (float*)d_out;

    static int inited = 0;
    if (!inited) {
        cudaFuncSetAttribute(gemm_hmma<1>, cudaFuncAttributeMaxDynamicSharedMemorySize, GSMEM_BYTES);
        cudaFuncSetAttribute(gemm_hmma<2>, cudaFuncAttributeMaxDynamicSharedMemorySize, GSMEM_BYTES);
        cudaFuncSetAttribute(attn_hmma,    cudaFuncAttributeMaxDynamicSharedMemorySize, ATTN_SMEM_BYTES);
        inited = 1;
    }

    __nv_bfloat16 *ah, *al, *wqh, *wql, *wph, *wpl;
    cudaGetSymbolAddress((void**)&ah,  g_ah);
    cudaGetSymbolAddress((void**)&al,  g_al);
    cudaGetSymbolAddress((void**)&wqh, g_wqh);
    cudaGetSymbolAddress((void**)&wql, g_wql);
    cudaGetSymbolAddress((void**)&wph, g_wph);
    cudaGetSymbolAddress((void**)&wpl, g_wpl);

    // 1) split x and weights to bf16 hi/lo
    split_kernel<<<(M_*C_/4 + 255)/256, 256>>>(x, ah, al, M_*C_/4);
    split_kernel<<<(3*C_*C_/4 + 255)/256, 256>>>(Wqkv, wqh, wql, 3*C_*C_/4);
    split_kernel<<<(C_*C_/4 + 255)/256, 256>>>(Wproj, wph, wpl, C_*C_/4);

    // 2) QKV projection -> split bf16 q/k/v (q pre-scaled for base-2 softmax)
    gemm_hmma<1><<<dim3(3*C_/256, M_/128), 256, GSMEM_BYTES>>>(ah, al, wqh, wql, bqkv, nullptr);

    // 3) causal flash attention (HMMA) -> split bf16 y into g_ah/g_al
    attn_hmma<<<dim3(T_/128, NH_, B_), 256, ATTN_SMEM_BYTES>>>();

    // 4) output projection -> d_out
    gemm_hmma<2><<<dim3(C_/256, M_/128), 256, GSMEM_BYTES>>>(ah, al, wph, wpl, bproj, out);
}

// round 11
// speedup vs baseline: 1.8059x; 1.8059x over previous
#include <cuda_runtime.h>
#include <cuda_fp16.h>
#include <cstdint>

#define B_  4
#define T_  2048
#define C_  1024
#define NH_ 16
#define HS_ 64
#define M_  (B_*T_)      // 8192

#define QSCALE 0.18033688011112042f   // 0.125 * log2(e)

// ---------------- scratch (__device__ globals; no allocation) ---------------
__device__ __half g_qh[B_*NH_*T_*HS_];   // q hi (scaled)
__device__ __half g_ql[B_*NH_*T_*HS_];   // q lo (scaled)
__device__ __half g_kh[B_*NH_*T_*HS_];   // k (single fp16)
__device__ __half g_vh[B_*NH_*T_*HS_];   // v (single fp16)
__device__ __half g_ah[M_*C_];           // activation hi (x, then y)
__device__ __half g_al[M_*C_];           // activation lo
__device__ __half g_wqh[3*C_*C_];        // Wqkv fp16
__device__ __half g_wph[C_*C_];          // Wproj fp16

// ---------------- helpers ---------------------------------------------------
__device__ __forceinline__ uint32_t smem_u32(const void* p) {
    uint32_t a;
    asm("{ .reg .u64 t; cvta.to.shared.u64 t, %1; cvt.u32.u64 %0, t; }" : "=r"(a) : "l"(p));
    return a;
}
#define LDMX4(r0, r1, r2, r3, addr)                                              \
    asm volatile("ldmatrix.sync.aligned.m8n8.x4.shared.b16 {%0,%1,%2,%3}, [%4];" \
        : "=r"(r0), "=r"(r1), "=r"(r2), "=r"(r3) : "r"(addr))
#define LDMX4T(r0, r1, r2, r3, addr)                                             \
    asm volatile("ldmatrix.sync.aligned.m8n8.x4.trans.shared.b16 {%0,%1,%2,%3}, [%4];" \
        : "=r"(r0), "=r"(r1), "=r"(r2), "=r"(r3) : "r"(addr))
#define MMAH(d, a0, a1, a2, a3, b0, b1)                                          \
    asm volatile("mma.sync.aligned.m16n8k16.row.col.f32.f16.f16.f32 "            \
        "{%0,%1,%2,%3}, {%4,%5,%6,%7}, {%8,%9}, {%0,%1,%2,%3};"                  \
        : "+f"((d)[0]), "+f"((d)[1]), "+f"((d)[2]), "+f"((d)[3])                 \
        : "r"(a0), "r"(a1), "r"(a2), "r"(a3), "r"(b0), "r"(b1))
#define CP16(dst, src)                                                            \
    asm volatile("cp.async.cg.shared.global [%0], [%1], 16;" :: "r"(dst), "l"(src))
#define CPCOMMIT() asm volatile("cp.async.commit_group;")
#define CPWAIT1()  asm volatile("cp.async.wait_group 1;")
#define CPWAIT0()  asm volatile("cp.async.wait_group 0;")

__device__ __forceinline__ float ex2f(float x) {
    float r;
    asm("ex2.approx.ftz.f32 %0, %1;" : "=f"(r) : "f"(x));
    return r;
}
__device__ __forceinline__ float rcpf(float x) {
    float r;
    asm("rcp.approx.ftz.f32 %0, %1;" : "=f"(r) : "f"(x));
    return r;
}
__device__ __forceinline__ uint32_t pack2h(float x, float y) {
    __half2 t; t.x = __float2half_rn(x); t.y = __float2half_rn(y);
    return *(uint32_t*)&t;
}
__device__ __forceinline__ void split2h(float x, float y, uint32_t& hi, uint32_t& lo) {
    __half hx = __float2half_rn(x), hy = __float2half_rn(y);
    __half2 h; h.x = hx; h.y = hy;
    __half2 l;
    l.x = __float2half_rn(x - __half2float(hx));
    l.y = __float2half_rn(y - __half2float(hy));
    hi = *(uint32_t*)&h; lo = *(uint32_t*)&l;
}

// ---------------- split fp32 -> fp16 hi/lo -----------------------------------
__global__ __launch_bounds__(256)
void split_kernel(const float* __restrict__ src, __half* __restrict__ hi,
                  __half* __restrict__ lo, int n4)
{
    int i = blockIdx.x * 256 + threadIdx.x;
    if (i >= n4) return;
    float4 v = ((const float4*)src)[i];
    uint32_t h0, l0, h1, l1;
    split2h(v.x, v.y, h0, l0);
    split2h(v.z, v.w, h1, l1);
    ((uint32_t*)hi)[i*2]   = h0;
    ((uint32_t*)hi)[i*2+1] = h1;
    ((uint32_t*)lo)[i*2]   = l0;
    ((uint32_t*)lo)[i*2+1] = l1;
}

// ---------------- convert fp32 -> fp16 ---------------------------------------
__global__ __launch_bounds__(256)
void tohalf_kernel(const float* __restrict__ src, __half* __restrict__ dst, int n4)
{
    int i = blockIdx.x * 256 + threadIdx.x;
    if (i >= n4) return;
    float4 v = ((const float4*)src)[i];
    ((uint32_t*)dst)[i*2]   = pack2h(v.x, v.y);
    ((uint32_t*)dst)[i*2+1] = pack2h(v.z, v.w);
}

// ---------------- HMMA GEMM (fp16 2-pass, cp.async 3-stage) ------------------
// Out[m,n] = sum_k A[m,k]*W[n,k] + bias[n];  A split (Ah+Al), W rounded (Wh).
// Pass0: Ah*Wh, Pass1: Al*Wh  ->  full-precision A times fp16(W).
// CTA 128x128, BK=32, 8 warps (4x2), warp 32x64.  (R8-proven shape)
// MODE 1: epilogue -> q (split fp16, scaled) / k / v (fp16).
// MODE 2: Out = fp32 + bias.
#define PADK 40                       // fp16 per smem row (80 B)
#define GSTAGE_B (128*PADK*2)         // 10240 B per matrix per stage
#define GSTAGE   (2*GSTAGE_B)
#define GSMEM_BYTES (3 * GSTAGE)      // 61440 B

template <int MODE>
__global__ __launch_bounds__(256, 2)
void gemm_hmma(const __half* __restrict__ Ah, const __half* __restrict__ Al,
               const __half* __restrict__ Wh,
               const float* __restrict__ bias, float* __restrict__ Out)
{
    extern __shared__ __half gsm[];
    const uint32_t sbase = smem_u32(gsm);
    const int tid  = threadIdx.x;
    const int bm   = blockIdx.y, bn = blockIdx.x;
    const int warp = tid >> 5, lane = tid & 31;
    const int warpM = warp & 3, warpN = warp >> 2;

    const int lrow = tid >> 1;
    const int lcol = (tid & 1) * 16;
    const size_t arowoff = (size_t)(bm * 128 + lrow) * C_ + lcol;
    const size_t browoff = (size_t)(bn * 128 + lrow) * C_ + lcol;
    const uint32_t dstoff = (uint32_t)(lrow * PADK + lcol) * 2;

    const int rowA_l = warpM * 32 + (lane & 15);
    const int colA_l = (lane >> 4) * 8;
    const int rowB_l = warpN * 64 + (lane & 7) + ((lane >> 4) << 3);
    const int colB_l = ((lane >> 3) & 1) * 8;

    float acc[2][8][4];
#pragma unroll
    for (int mf = 0; mf < 2; mf++)
#pragma unroll
        for (int nf = 0; nf < 8; nf++)
#pragma unroll
            for (int r = 0; r < 4; r++) acc[mf][nf][r] = 0.f;

    const int NIT = 64;  // 2 passes * 32

    auto issue = [&](int s, int it) {
        const int pass = it >> 5;                // 0: Ah, 1: Al
        const int kb = (it & 31) * 32;
        const __half* Ap = pass ? Al : Ah;
        const uint32_t aDst = sbase + (uint32_t)s * GSTAGE + dstoff;
        const uint32_t bDst = aDst + GSTAGE_B;
        CP16(aDst,      Ap + arowoff + kb);
        CP16(aDst + 16, Ap + arowoff + kb + 8);
        CP16(bDst,      Wh + browoff + kb);
        CP16(bDst + 16, Wh + browoff + kb + 8);
    };

    issue(0, 0); CPCOMMIT();
    issue(1, 1); CPCOMMIT();

    for (int it = 0; it < NIT; it++) {
        CPWAIT1();
        __syncthreads();
        if (it + 2 < NIT) issue((it + 2) % 3, it + 2);
        CPCOMMIT();
        const uint32_t aBase = sbase + (uint32_t)(it % 3) * GSTAGE;
        const uint32_t bBase = aBase + GSTAGE_B;
#pragma unroll
        for (int k16 = 0; k16 < 2; k16++) {
            uint32_t a0[4], a1[4];
            LDMX4(a0[0], a0[1], a0[2], a0[3],
                  aBase + (uint32_t)((rowA_l)      * PADK + colA_l + k16 * 16) * 2);
            LDMX4(a1[0], a1[1], a1[2], a1[3],
                  aBase + (uint32_t)((rowA_l + 16) * PADK + colA_l + k16 * 16) * 2);
#pragma unroll
            for (int ng = 0; ng < 4; ng++) {
                uint32_t b[4];
                LDMX4(b[0], b[1], b[2], b[3],
                      bBase + (uint32_t)((rowB_l + ng * 16) * PADK + colB_l + k16 * 16) * 2);
                MMAH(acc[0][ng*2],   a0[0], a0[1], a0[2], a0[3], b[0], b[1]);
                MMAH(acc[0][ng*2+1], a0[0], a0[1], a0[2], a0[3], b[2], b[3]);
                MMAH(acc[1][ng*2],   a1[0], a1[1], a1[2], a1[3], b[0], b[1]);
                MMAH(acc[1][ng*2+1], a1[0], a1[1], a1[2], a1[3], b[2], b[3]);
            }
        }
    }

    // ---------------- epilogue ----------------
    const int mrow0 = bm * 128 + warpM * 32;
    const int ncol0 = bn * 128 + warpN * 64;
    const int lq = lane >> 2, lr = lane & 3;
#pragma unroll
    for (int mf = 0; mf < 2; mf++) {
#pragma unroll
        for (int nf = 0; nf < 8; nf++) {
            const int n = ncol0 + nf * 8 + lr * 2;
            const float b0 = bias[n], b1 = bias[n + 1];
#pragma unroll
            for (int half_ = 0; half_ < 2; half_++) {
                const int m = mrow0 + mf * 16 + lq + half_ * 8;
                float v0 = acc[mf][nf][half_ * 2 + 0] + b0;
                float v1 = acc[mf][nf][half_ * 2 + 1] + b1;
                if (MODE == 1) {
                    const int sel = n >> 10;
                    const int h   = (n & 1023) >> 6;
                    const int hs0 = n & 63;
                    const int bb = m >> 11, t = m & 2047;
                    const size_t idx = (((size_t)(bb * NH_ + h) * T_ + t) << 6) + hs0;
                    if (sel == 0) {
                        uint32_t hi, lo;
                        split2h(v0 * QSCALE, v1 * QSCALE, hi, lo);
                        *(uint32_t*)(g_qh + idx) = hi;
                        *(uint32_t*)(g_ql + idx) = lo;
                    } else if (sel == 1) {
                        *(uint32_t*)(g_kh + idx) = pack2h(v0, v1);
                    } else {
                        *(uint32_t*)(g_vh + idx) = pack2h(v0, v1);
                    }
                } else {
                    float2 v; v.x = v0; v.y = v1;
                    *(float2*)(Out + (size_t)m * C_ + n) = v;
                }
            }
        }
    }
}

// ---------------- HMMA flash attention (fp16 2-pass) -------------------------
// BM=128 (8 warps x m16), BN=64. QK: qh*kh + ql*kh (full Q x fp16 K).
// PV: ph*vh + pl*vh (full P x fp16 V). Base-2 softmax, Q pre-scaled.
// KV single fp16 -> halved smem + cp.async traffic vs bf16x3 version.
#define AP 72                         // padded row stride (fp16)
#define SQH 0
#define SQL (128*AP)
#define SKV0 (2*128*AP)
#define KVSTAGE (2*64*AP)             // kh + vh per stage
#define ATTN_SMEM_BYTES ((SKV0 + 2*KVSTAGE) * 2)   // 73728 B

__global__ __launch_bounds__(256, 2)
void attn_hmma()
{
    extern __shared__ __half asm_[];
    const uint32_t sbase = smem_u32(asm_);
    const int tid  = threadIdx.x;
    const int warp = tid >> 5, lane = tid & 31;
    const int lq = lane >> 2, lr = lane & 3;

    const int qt = (int)gridDim.x - 1 - (int)blockIdx.x;
    const int h  = blockIdx.y;
    const int b  = blockIdx.z;
    const size_t bh = (size_t)(b * NH_ + h) * (T_ * HS_);

    // ---- load Q (hi+lo) into smem ----
#pragma unroll
    for (int i = 0; i < 4; i++) {
        int c = i * 256 + tid;
        int row = c >> 3, col = (c & 7) * 8;
        const size_t src = bh + (size_t)(qt * 128 + row) * 64 + col;
        *(uint4*)(asm_ + SQH + row * AP + col) = *(const uint4*)(g_qh + src);
        *(uint4*)(asm_ + SQL + row * AP + col) = *(const uint4*)(g_ql + src);
    }

    auto issue_kv = [&](int s, int kv) {
        const uint32_t stg = sbase + (uint32_t)(SKV0 + s * KVSTAGE) * 2;
#pragma unroll
        for (int i = 0; i < 2; i++) {
            int c = i * 256 + tid;
            int row = c >> 3, col = (c & 7) * 8;
            const size_t src = bh + (size_t)(kv * 64 + row) * 64 + col;
            const uint32_t d = stg + (uint32_t)(row * AP + col) * 2;
            CP16(d,             g_kh + src);
            CP16(d + (64*AP)*2, g_vh + src);
        }
    };

    const int kvmax = 2 * qt + 1;
    issue_kv(0, 0); CPCOMMIT();

    const int mr = qt * 128 + warp * 16;
    float m0 = -1e30f, m1 = -1e30f, l0 = 0.f, l1 = 0.f;
    float oacc[8][4];
#pragma unroll
    for (int d = 0; d < 8; d++)
#pragma unroll
        for (int r = 0; r < 4; r++) oacc[d][r] = 0.f;

    const uint32_t qhB = sbase + SQH * 2;
    const uint32_t qlB = sbase + SQL * 2;
    const int rowA_l = warp * 16 + (lane & 15);
    const int colA_l = (lane >> 4) * 8;
    const int rowB_l = (lane & 7) + ((lane >> 4) << 3);
    const int colB_l = ((lane >> 3) & 1) * 8;

    for (int kv = 0; kv <= kvmax; kv++) {
        CPWAIT0();
        __syncthreads();
        if (kv < kvmax) issue_kv((kv + 1) & 1, kv + 1);
        CPCOMMIT();

        const int nc = kv * 64;
        if (nc <= mr + 15) {
            const uint32_t stg = sbase + (uint32_t)(SKV0 + (kv & 1) * KVSTAGE) * 2;
            const uint32_t khB = stg;
            const uint32_t vhB = stg + (64*AP)*2;

            // ---- S = QK^T (2-pass: qh*kh + ql*kh) ----
            float s[8][4];
#pragma unroll
            for (int jn = 0; jn < 8; jn++)
#pragma unroll
                for (int r = 0; r < 4; r++) s[jn][r] = 0.f;

#pragma unroll
            for (int pass = 0; pass < 2; pass++) {
                const uint32_t aB = pass ? qlB : qhB;
#pragma unroll
                for (int k16 = 0; k16 < 4; k16++) {
                    uint32_t a[4];
                    LDMX4(a[0], a[1], a[2], a[3],
                          aB + (uint32_t)(rowA_l * AP + k16 * 16 + colA_l) * 2);
#pragma unroll
                    for (int nb = 0; nb < 4; nb++) {
                        uint32_t bb[4];
                        LDMX4(bb[0], bb[1], bb[2], bb[3],
                              khB + (uint32_t)((nb * 16 + rowB_l) * AP + k16 * 16 + colB_l) * 2);
                        MMAH(s[nb*2],   a[0], a[1], a[2], a[3], bb[0], bb[1]);
                        MMAH(s[nb*2+1], a[0], a[1], a[2], a[3], bb[2], bb[3]);
                    }
                }
            }

            // ---- causal mask ----
            if (nc + 63 > mr) {
#pragma unroll
                for (int jn = 0; jn < 8; jn++)
#pragma unroll
                    for (int e = 0; e < 2; e++) {
                        const int col = nc + jn * 8 + lr * 2 + e;
                        if (col > mr + lq)     s[jn][e]     = -1e30f;
                        if (col > mr + lq + 8) s[jn][e + 2] = -1e30f;
                    }
            }

            // ---- online softmax (base 2) ----
            float mx0 = -1e30f, mx1 = -1e30f;
#pragma unroll
            for (int jn = 0; jn < 8; jn++) {
                mx0 = fmaxf(mx0, fmaxf(s[jn][0], s[jn][1]));
                mx1 = fmaxf(mx1, fmaxf(s[jn][2], s[jn][3]));
            }
            mx0 = fmaxf(mx0, __shfl_xor_sync(0xffffffffu, mx0, 1));
            mx0 = fmaxf(mx0, __shfl_xor_sync(0xffffffffu, mx0, 2));
            mx1 = fmaxf(mx1, __shfl_xor_sync(0xffffffffu, mx1, 1));
            mx1 = fmaxf(mx1, __shfl_xor_sync(0xffffffffu, mx1, 2));
            const float mn0 = fmaxf(m0, mx0), mn1 = fmaxf(m1, mx1);
            const float c0 = ex2f(m0 - mn0), c1 = ex2f(m1 - mn1);
            m0 = mn0; m1 = mn1;
            float rs0 = 0.f, rs1 = 0.f;
#pragma unroll
            for (int jn = 0; jn < 8; jn++) {
                s[jn][0] = ex2f(s[jn][0] - mn0);
                s[jn][1] = ex2f(s[jn][1] - mn0);
                s[jn][2] = ex2f(s[jn][2] - mn1);
                s[jn][3] = ex2f(s[jn][3] - mn1);
                rs0 += s[jn][0] + s[jn][1];
                rs1 += s[jn][2] + s[jn][3];
            }
            rs0 += __shfl_xor_sync(0xffffffffu, rs0, 1);
            rs0 += __shfl_xor_sync(0xffffffffu, rs0, 2);
            rs1 += __shfl_xor_sync(0xffffffffu, rs1, 1);
            rs1 += __shfl_xor_sync(0xffffffffu, rs1, 2);
            l0 = l0 * c0 + rs0;
            l1 = l1 * c1 + rs1;
#pragma unroll
            for (int d = 0; d < 8; d++) {
                oacc[d][0] *= c0; oacc[d][1] *= c0;
                oacc[d][2] *= c1; oacc[d][3] *= c1;
            }

            // ---- pack P into A-fragments (fp16 hi/lo) ----
            uint32_t ph[4][4], pl[4][4];
#pragma unroll
            for (int kk = 0; kk < 4; kk++) {
                const int j0 = kk * 2, j1 = kk * 2 + 1;
                split2h(s[j0][0], s[j0][1], ph[kk][0], pl[kk][0]);
                split2h(s[j0][2], s[j0][3], ph[kk][1], pl[kk][1]);
                split2h(s[j1][0], s[j1][1], ph[kk][2], pl[kk][2]);
                split2h(s[j1][2], s[j1][3], ph[kk][3], pl[kk][3]);
            }

            // ---- O += P V (2-pass: ph*vh + pl*vh) ----
#pragma unroll
            for (int kk = 0; kk < 4; kk++) {
#pragma unroll
                for (int db = 0; db < 4; db++) {
                    uint32_t v[4];
                    LDMX4T(v[0], v[1], v[2], v[3],
                           vhB + (uint32_t)((kk * 16 + (lane & 15)) * AP + db * 16 + colA_l) * 2);
                    MMAH(oacc[db*2],   ph[kk][0], ph[kk][1], ph[kk][2], ph[kk][3], v[0], v[1]);
                    MMAH(oacc[db*2+1], ph[kk][0], ph[kk][1], ph[kk][2], ph[kk][3], v[2], v[3]);
                    MMAH(oacc[db*2],   pl[kk][0], pl[kk][1], pl[kk][2], pl[kk][3], v[0], v[1]);
                    MMAH(oacc[db*2+1], pl[kk][0], pl[kk][1], pl[kk][2], pl[kk][3], v[2], v[3]);
                }
            }
        }
        __syncthreads();
    }

    // ---- epilogue: normalize, split fp16, write y into g_ah/g_al ----
    const float inv0 = rcpf(l0), inv1 = rcpf(l1);
    const int t0 = qt * 128 + warp * 16 + lq;
    const size_t base0 = ((size_t)b * T_ + t0) * C_ + h * 64;
    const size_t base1 = base0 + (size_t)8 * C_;
#pragma unroll
    for (int jn = 0; jn < 8; jn++) {
        const int col = jn * 8 + lr * 2;
        uint32_t hi, lo;
        split2h(oacc[jn][0] * inv0, oacc[jn][1] * inv0, hi, lo);
        *(uint32_t*)(g_ah + base0 + col) = hi;
        *(uint32_t*)(g_al + base0 + col) = lo;
        split2h(oacc[jn][2] * inv1, oacc[jn][3] * inv1, hi, lo);
        *(uint32_t*)(g_ah + base1 + col) = hi;
        *(uint32_t*)(g_al + base1 + col) = lo;
    }
}

// ---------------------------------------------------------------------------
extern "C" void kernel_launch(void* const* d_in, const int* in_sizes, int n_in,
                              void* d_out, int out_size)
{
    (void)in_sizes; (void)n_in; (void)out_size;
    const float* x     = (const float*)d_in[0];
    const float* Wqkv  = (const float*)d_in[1];
    const float* bqkv  = (const float*)d_in[2];
    const float* Wproj = (const float*)d_in[3];
    const float* bproj = (const float*)d_in[4];
    float* out = (float*)d_out;

    static int inited = 0;
    if (!inited) {
        cudaFuncSetAttribute(gemm_hmma<1>, cudaFuncAttributeMaxDynamicSharedMemorySize, GSMEM_BYTES);
        cudaFuncSetAttribute(gemm_hmma<2>, cudaFuncAttributeMaxDynamicSharedMemorySize, GSMEM_BYTES);
        cudaFuncSetAttribute(attn_hmma,    cudaFuncAttributeMaxDynamicSharedMemorySize, ATTN_SMEM_BYTES);
        inited = 1;
    }

    __half *ah, *al, *wqh, *wph;
    cudaGetSymbolAddress((void**)&ah,  g_ah);
    cudaGetSymbolAddress((void**)&al,  g_al);
    cudaGetSymbolAddress((void**)&wqh, g_wqh);
    cudaGetSymbolAddress((void**)&wph, g_wph);

    // 1) split x (fp16 hi/lo); convert weights to fp16
    split_kernel<<<(M_*C_/4 + 255)/256, 256>>>(x, ah, al, M_*C_/4);
    tohalf_kernel<<<(3*C_*C_/4 + 255)/256, 256>>>(Wqkv, wqh, 3*C_*C_/4);
    tohalf_kernel<<<(C_*C_/4 + 255)/256, 256>>>(Wproj, wph, C_*C_/4);

    // 2) QKV projection -> q (split, scaled) / k / v (fp16)
    gemm_hmma<1><<<dim3(3*C_/128, M_/128), 256, GSMEM_BYTES>>>(ah, al, wqh, bqkv, nullptr);

    // 3) causal flash attention -> y (split fp16) into g_ah/g_al
    attn_hmma<<<dim3(T_/128, NH_, B_), 256, ATTN_SMEM_BYTES>>>();

    // 4) output projection -> d_out
    gemm_hmma<2><<<dim3(C_/128, M_/128), 256, GSMEM_BYTES>>>(ah, al, wph, bproj, out);
}